// round 14
// baseline (speedup 1.0000x reference)
#include <cuda_runtime.h>
#include <cuda_fp16.h>
#include <cstdint>
#include <math.h>

// feature: [8,1024,64,64] f32 ; conv_w: [1024,1049] ; conv_b: [1024] ; out f32 same shape
// cat channels: 0..1023 feature, 1024..1048 corr (j = cc*5+r). K padded to 1088 for layout;
// only k<1056 is ever computed (W zero for k>=1049).

#define B_      8
#define C_      1024
#define HW_     4096
#define OC_     1024
#define KTOT    1088      // layout stride (17 * 64)
#define KREAL   1049
#define NG      8

template<int N> struct IC { static constexpr int value = N; };

// ---------------- scratch ----------------
__device__ __half g_Wh[OC_ * KTOT];                          // fp16 weights, zero-padded
__device__ __half g_Ah[(size_t)B_ * KTOT * HW_];             // fp16 A [b][1088][4096]
__device__ __align__(16) float g_sspart[NG * B_ * HW_];
__device__ __align__(16) float g_inv[B_ * HW_];
__device__ __align__(16) float g_accpart[(size_t)NG * B_ * 25 * HW_];

// ---------------- f32x2 helpers ----------------
typedef unsigned long long u64t;
__device__ __forceinline__ u64t pk2(float a, float b) {
    u64t r; asm("mov.b64 %0, {%1, %2};" : "=l"(r) : "f"(a), "f"(b)); return r;
}
__device__ __forceinline__ void fma2(u64t& d, u64t a, u64t b) {
    asm("fma.rn.f32x2 %0, %1, %2, %0;" : "+l"(d) : "l"(a), "l"(b));
}
__device__ __forceinline__ float2 up2(u64t a) {
    float2 r; asm("mov.b64 {%0, %1}, %2;" : "=f"(r.x), "=f"(r.y) : "l"(a)); return r;
}

// ============================================================
// fused: convW (vectorized, conv_w -> fp16 padded) + inv
// ============================================================
__global__ void fuse_kernel(const float* __restrict__ w) {
    int idx = blockIdx.x * 256 + threadIdx.x;
    if (idx < OC_ * KTOT / 8) {
        int o = idx / (KTOT / 8), seg = idx - o * (KTOT / 8);
        int k0 = seg * 8;
        __half h[8];
#pragma unroll
        for (int i = 0; i < 8; i++) {
            int k = k0 + i;
            h[i] = __float2half((k < KREAL) ? w[o * KREAL + k] : 0.0f);
        }
        *(uint4*)&g_Wh[o * KTOT + k0] = *(uint4*)h;
    }
    if (idx < B_ * HW_) {
        float ssv = 0.0f;
#pragma unroll
        for (int g = 0; g < NG; g++) ssv += g_sspart[g * B_ * HW_ + idx];
        g_inv[idx] = 1.0f / fmaxf(sqrtf(ssv), 1e-12f);
    }
}

// ============================================================
// corr partials + sumsq + fp16 feature write.
// 32x32 tile, 2x2 px/thread, f32x2 FMA, NG=8 groups of 128 ch.
// 3 smem buffers (dynamic), one __syncthreads/iter.
// Order per iter: wait -> sync -> issue load(it+2) -> compute(it).
// Sync separates compute(it-1) (all warps) from the overwrite of buffer (it-1)%3.
// ============================================================
#define CORR_BUF (4 * 36 * 40)            // floats per buffer
#define CORR_SMEM (3 * CORR_BUF * 4)      // 69120 B

__global__ __launch_bounds__(256, 2) void corr_kernel(const float* __restrict__ feat) {
    extern __shared__ float tile[];       // [3][4][36*40]

    const int tid = threadIdx.x;
    const int tx = tid & 15, ty = tid >> 4;
    const int x0 = blockIdx.x * 32, y0 = blockIdx.y * 32;
    const int b = blockIdx.z >> 3, g = blockIdx.z & 7;
    const float* fb = feat + (size_t)b * C_ * HW_;
    __half* ah = g_Ah + ((size_t)b * KTOT << 12);
    const int cbase = g * 128;

    u64t acc2[25][2];
    u64t ss2[2];
#pragma unroll
    for (int j = 0; j < 25; j++) { acc2[j][0] = 0ull; acc2[j][1] = 0ull; }
    ss2[0] = 0ull; ss2[1] = 0ull;

    auto load4 = [&](int c0, int buf) {
        float* base = tile + buf * CORR_BUF;
#pragma unroll 2
        for (int u = tid; u < 1440; u += 256) {
            int cc = u / 360, pos = u - cc * 360;
            int j = pos / 10, i = pos - j * 10;
            int gy = y0 - 2 + j;
            int gx0 = x0 - 4 + i * 4;
            bool valid = ((unsigned)gy < 64u) && ((unsigned)gx0 < 64u);
            const float* src = fb + (size_t)(c0 + cc) * HW_ + (valid ? (gy * 64 + gx0) : 0);
            unsigned dst = (unsigned)__cvta_generic_to_shared(base + cc * 1440 + j * 40 + i * 4);
            int sz = valid ? 16 : 0;
            asm volatile("cp.async.ca.shared.global [%0], [%1], 16, %2;\n"
                         :: "r"(dst), "l"(src), "r"(sz));
        }
    };

    load4(cbase, 0);
    asm volatile("cp.async.commit_group;\n");
    load4(cbase + 4, 1);
    asm volatile("cp.async.commit_group;\n");

    for (int it = 0; it < 32; ++it) {
        // buffer `it` ready when all but the newest pending group are done (in-order FIFO)
        asm volatile("cp.async.wait_group 1;\n");
        __syncthreads();
        if (it + 2 < 32) load4(cbase + (it + 2) * 4, (it + 2) % 3);
        asm volatile("cp.async.commit_group;\n");    // real or empty: keeps accounting uniform

        const float* tb = tile + (it % 3) * CORR_BUF;
#pragma unroll
        for (int q = 0; q < 4; q++) {
            const float* tq = tb + q * 1440;
            const int c = cbase + it * 4 + q;

            // stage the two cen rows (rr=2,3); cen pair == t[2] of those rows
            float2 P2[3], P3[3];
            {
                const float* r2 = &tq[(2 * ty + 2) * 40 + 2 * tx + 2];
#pragma unroll
                for (int i = 0; i < 3; i++) {
                    P2[i] = *(const float2*)(r2 + 2 * i);
                    P3[i] = *(const float2*)(r2 + 40 + 2 * i);
                }
            }
            u64t cen2[2];
            cen2[0] = pk2(P2[1].x, P2[1].y);
            cen2[1] = pk2(P3[1].x, P3[1].y);
            fma2(ss2[0], cen2[0], cen2[0]);
            fma2(ss2[1], cen2[1], cen2[1]);
            {
                __half2 h0 = __floats2half2_rn(P2[1].x, P2[1].y);
                __half2 h1 = __floats2half2_rn(P3[1].x, P3[1].y);
                *(__half2*)&ah[((size_t)c << 12) + (y0 + 2 * ty + 0) * 64 + x0 + 2 * tx] = h0;
                *(__half2*)&ah[((size_t)c << 12) + (y0 + 2 * ty + 1) * 64 + x0 + 2 * tx] = h1;
            }
#pragma unroll
            for (int rr = 0; rr < 6; rr++) {
                float2 p0, p1, p2;
                if (rr == 2)      { p0 = P2[0]; p1 = P2[1]; p2 = P2[2]; }
                else if (rr == 3) { p0 = P3[0]; p1 = P3[1]; p2 = P3[2]; }
                else {
                    const float* rp = &tq[(2 * ty + rr) * 40 + 2 * tx + 2];
                    p0 = *(const float2*)(rp);
                    p1 = *(const float2*)(rp + 2);
                    p2 = *(const float2*)(rp + 4);
                }
                u64t t[5];
                t[0] = pk2(p0.x, p0.y);
                t[1] = pk2(p0.y, p1.x);
                t[2] = pk2(p1.x, p1.y);
                t[3] = pk2(p1.y, p2.x);
                t[4] = pk2(p2.x, p2.y);
#pragma unroll
                for (int cc = 0; cc < 5; cc++) {
                    if (rr <= 4) fma2(acc2[cc * 5 + rr][0], t[cc], cen2[0]);
                    if (rr >= 1) fma2(acc2[cc * 5 + rr - 1][1], t[cc], cen2[1]);
                }
            }
        }
    }

#pragma unroll
    for (int yy = 0; yy < 2; yy++) {
        int p = (y0 + 2 * ty + yy) * 64 + x0 + 2 * tx;
        *(float2*)&g_sspart[(g * B_ + b) * HW_ + p] = up2(ss2[yy]);
#pragma unroll
        for (int j = 0; j < 25; j++)
            *(float2*)&g_accpart[((size_t)(g * B_ + b) * 25 + j) * HW_ + p] = up2(acc2[j][yy]);
    }
}

// ============================================================
// combine: normalized corr -> fp16 A channels 1024..1055 (2 px/thread)
// ============================================================
__global__ void combine_kernel() {
    int idx = blockIdx.x * 256 + threadIdx.x;     // B_*32*HW_/2
    if (idx >= B_ * 32 * HW_ / 2) return;
    int ph = idx & (HW_ / 2 - 1);                 // pixel pair index
    int j = (idx >> 11) & 31;
    int b = idx >> 16;
    int p = ph * 2;
    float2 v = make_float2(0.0f, 0.0f);
    if (j < 25) {
        int y = p >> 6, x = p & 63;
        int ccs = j / 5, r = j - ccs * 5;
        int tyy = y + r - 2;
        if ((unsigned)tyy < 64u) {
            float2 a = make_float2(0.0f, 0.0f);
#pragma unroll
            for (int g = 0; g < NG; g++) {
                float2 t = *(const float2*)&g_accpart[((size_t)(g * B_ + b) * 25 + j) * HW_ + p];
                a.x += t.x; a.y += t.y;
            }
            float2 ic = *(const float2*)&g_inv[b * HW_ + p];
            int txx0 = x + ccs - 2, txx1 = txx0 + 1;
            if ((unsigned)txx0 < 64u)
                v.x = a.x * ic.x * g_inv[b * HW_ + tyy * 64 + txx0];
            if ((unsigned)txx1 < 64u)
                v.y = a.y * ic.y * g_inv[b * HW_ + tyy * 64 + txx1];
        }
    }
    *(__half2*)&g_Ah[((size_t)(b * KTOT + C_ + j) << 12) + p] = __floats2half2_rn(v.x, v.y);
}

// ============================================================
// GEMM  out[b,o,p] = relu( sum_k Wh[o,k]*Ah[b,k,p] + bias[o] )
// CTA tile 128p x 128o x 64k, 256 threads, 3-stage cp.async, 2 CTAs/SM.
// Last k-tile half depth (k 1024..1055); k>=1056 has zero weights.
// ============================================================
#define NKT 17
#define A_STAGE 17408       // 64*136*2
#define B_STAGE 18432       // 128*72*2
#define NSTG 3
#define GEMM_SMEM (NSTG * (A_STAGE + B_STAGE))

__global__ __launch_bounds__(256, 2) void gemm_kernel(const float* __restrict__ bias,
                                                      float* __restrict__ out) {
    extern __shared__ __align__(16) unsigned char SM[];
    __half* As[NSTG];
    __half* Bs[NSTG];
#pragma unroll
    for (int s = 0; s < NSTG; s++) {
        As[s] = (__half*)(SM + s * (A_STAGE + B_STAGE));
        Bs[s] = (__half*)(SM + s * (A_STAGE + B_STAGE) + A_STAGE);
    }
    float* Ep = (float*)SM;   // [128][33] epilogue staging

    const int tid = threadIdx.x;
    const int lane = tid & 31, wid = tid >> 5;
    const int wm = wid & 3, wn = wid >> 2;
    const int o0 = blockIdx.x * 128;
    const int p0 = blockIdx.y * 128;
    const int b  = blockIdx.z;

    const __half* aBase = g_Ah + ((size_t)b * KTOT << 12) + p0;

    float accv[2][8][4];
#pragma unroll
    for (int i = 0; i < 2; i++)
#pragma unroll
        for (int j = 0; j < 8; j++)
#pragma unroll
            for (int e = 0; e < 4; e++) accv[i][j][e] = 0.0f;

    auto loadStage = [&](int kt, int buf) {
        const bool last = (kt == NKT - 1);
        // A: [k 64][m 128] fp16 (last: 32 rows)
#pragma unroll
        for (int s = 0; s < 4; s++) {
            if (last && s >= 2) break;
            int u = tid + s * 256;
            int row = u >> 4, ch = u & 15;
            const __half* src = aBase + (((size_t)(kt * 64 + row)) << 12) + ch * 8;
            unsigned dst = (unsigned)__cvta_generic_to_shared(As[buf] + row * 136 + ch * 8);
            asm volatile("cp.async.cg.shared.global [%0], [%1], 16;\n" :: "r"(dst), "l"(src));
        }
        // B: [n 128][k 64] fp16 (last: k cols 0..31)
#pragma unroll
        for (int s = 0; s < 4; s++) {
            int u = tid + s * 256;
            int orow = u >> 3, q = u & 7;
            if (last && q >= 4) continue;
            const __half* src = g_Wh + (size_t)(o0 + orow) * KTOT + kt * 64 + q * 8;
            unsigned dst = (unsigned)__cvta_generic_to_shared(Bs[buf] + orow * 72 + q * 8);
            asm volatile("cp.async.cg.shared.global [%0], [%1], 16;\n" :: "r"(dst), "l"(src));
        }
        asm volatile("cp.async.commit_group;\n");
    };

    auto compute = [&](int buf, auto nksC) {
        constexpr int NKS = decltype(nksC)::value;
#pragma unroll
        for (int ks = 0; ks < NKS; ks++) {
            const int kb = ks * 16;
            unsigned a[2][4];
#pragma unroll
            for (int fm = 0; fm < 2; fm++) {
                int kk = kb + ((lane >> 4) & 1) * 8 + (lane & 7);
                int mm = wm * 32 + fm * 16 + ((lane >> 3) & 1) * 8;
                unsigned addr = (unsigned)__cvta_generic_to_shared(As[buf] + kk * 136 + mm);
                asm volatile("ldmatrix.sync.aligned.m8n8.x4.trans.shared.b16 {%0,%1,%2,%3}, [%4];\n"
                             : "=r"(a[fm][0]), "=r"(a[fm][1]), "=r"(a[fm][2]), "=r"(a[fm][3])
                             : "r"(addr));
            }
            unsigned bf[4][4];
#pragma unroll
            for (int fp = 0; fp < 4; fp++) {
                int row = wn * 64 + fp * 16 + (lane & 7) + ((lane >> 4) & 1) * 8;
                int kcol = kb + ((lane >> 3) & 1) * 8;
                unsigned addr = (unsigned)__cvta_generic_to_shared(Bs[buf] + row * 72 + kcol);
                asm volatile("ldmatrix.sync.aligned.m8n8.x4.shared.b16 {%0,%1,%2,%3}, [%4];\n"
                             : "=r"(bf[fp][0]), "=r"(bf[fp][1]), "=r"(bf[fp][2]), "=r"(bf[fp][3])
                             : "r"(addr));
            }
#pragma unroll
            for (int fm = 0; fm < 2; fm++)
#pragma unroll
                for (int fp = 0; fp < 4; fp++)
#pragma unroll
                    for (int hh = 0; hh < 2; hh++) {
                        float* c = accv[fm][fp * 2 + hh];
                        asm volatile(
                            "mma.sync.aligned.m16n8k16.row.col.f32.f16.f16.f32 "
                            "{%0,%1,%2,%3}, {%4,%5,%6,%7}, {%8,%9}, {%0,%1,%2,%3};\n"
                            : "+f"(c[0]), "+f"(c[1]), "+f"(c[2]), "+f"(c[3])
                            : "r"(a[fm][0]), "r"(a[fm][1]), "r"(a[fm][2]), "r"(a[fm][3]),
                              "r"(bf[fp][hh * 2]), "r"(bf[fp][hh * 2 + 1]));
                    }
        }
    };

    loadStage(0, 0);
    loadStage(1, 1);

    for (int kt = 0; kt < NKT; ++kt) {
        asm volatile("cp.async.wait_group 1;\n");
        __syncthreads();
        if (kt + 2 < NKT) loadStage(kt + 2, (kt + 2) % NSTG);
        else asm volatile("cp.async.commit_group;\n");
        if (kt < NKT - 1) compute(kt % NSTG, IC<4>{});
        else              compute(kt % NSTG, IC<2>{});
    }

    __syncthreads();
#pragma unroll
    for (int ci = 0; ci < 4; ci++) {
        if (wn == (ci >> 1)) {
            const int fbase = (ci & 1) * 4;
#pragma unroll
            for (int fm = 0; fm < 2; fm++)
#pragma unroll
                for (int f = 0; f < 4; f++) {
                    int fn = fbase + f;
#pragma unroll
                    for (int e = 0; e < 4; e++) {
                        int row = wm * 32 + fm * 16 + (lane >> 2) + (e >> 1) * 8;
                        int col = f * 8 + 2 * (lane & 3) + (e & 1);
                        Ep[row * 33 + col] = accv[fm][fn][e];
                    }
                }
        }
        __syncthreads();
        for (int idx = tid; idx < 32 * 128; idx += 256) {
            int ol = idx >> 7, m = idx & 127;
            int o = o0 + ci * 32 + ol;
            float v = Ep[m * 33 + ol] + bias[o];
            out[(((size_t)(b * OC_ + o)) << 12) + p0 + m] = fmaxf(v, 0.0f);
        }
        __syncthreads();
    }
}

// ============================================================
extern "C" void kernel_launch(void* const* d_in, const int* in_sizes, int n_in,
                              void* d_out, int out_size) {
    const float* feat = (const float*)d_in[0];
    const float* w    = (const float*)d_in[1];
    const float* bias = (const float*)d_in[2];
    float* out = (float*)d_out;

    static bool attr_set = false;
    if (!attr_set) {
        cudaFuncSetAttribute(gemm_kernel, cudaFuncAttributeMaxDynamicSharedMemorySize,
                             GEMM_SMEM);
        cudaFuncSetAttribute(corr_kernel, cudaFuncAttributeMaxDynamicSharedMemorySize,
                             CORR_SMEM);
        attr_set = true;
    }

    corr_kernel<<<dim3(2, 2, B_ * NG), 256, CORR_SMEM>>>(feat);       // launch 1
    fuse_kernel<<<(OC_ * KTOT / 8 + 255) / 256, 256>>>(w);            // launch 2
    combine_kernel<<<(B_ * 32 * HW_ / 2) / 256, 256>>>();             // launch 3
    gemm_kernel<<<dim3(8, 32, B_), 256, GEMM_SMEM>>>(bias, out);      // launch 4 (captured)
}

// round 15
// speedup vs baseline: 1.1134x; 1.1134x over previous
#include <cuda_runtime.h>
#include <cuda_fp16.h>
#include <cstdint>
#include <math.h>

// feature: [8,1024,64,64] f32 ; conv_w: [1024,1049] ; conv_b: [1024] ; out f32 same shape
// cat channels: 0..1023 feature, 1024..1048 corr (j = cc*5+r). K padded to 1088 for layout;
// only k<1056 is ever computed (W zero for k>=1049).

#define B_      8
#define C_      1024
#define HW_     4096
#define OC_     1024
#define KTOT    1088      // layout stride (17 * 64)
#define KREAL   1049
#define NG      8

template<int N> struct IC { static constexpr int value = N; };

// ---------------- scratch ----------------
__device__ __half g_Wh[OC_ * KTOT];                          // fp16 weights, zero-padded
__device__ __half g_Ah[(size_t)B_ * KTOT * HW_];             // fp16 A [b][1088][4096]
__device__ __align__(16) float g_sspart[NG * B_ * HW_];
__device__ __align__(16) float g_inv[B_ * HW_];
__device__ __align__(16) float g_accpart[(size_t)NG * B_ * 25 * HW_];

// ---------------- f32x2 helpers ----------------
typedef unsigned long long u64t;
__device__ __forceinline__ u64t pk2(float a, float b) {
    u64t r; asm("mov.b64 %0, {%1, %2};" : "=l"(r) : "f"(a), "f"(b)); return r;
}
__device__ __forceinline__ void fma2(u64t& d, u64t a, u64t b) {
    asm("fma.rn.f32x2 %0, %1, %2, %0;" : "+l"(d) : "l"(a), "l"(b));
}
__device__ __forceinline__ float2 up2(u64t a) {
    float2 r; asm("mov.b64 {%0, %1}, %2;" : "=f"(r.x), "=f"(r.y) : "l"(a)); return r;
}

// ============================================================
// fused: convW (vectorized, conv_w -> fp16 padded) + inv
// ============================================================
__global__ void fuse_kernel(const float* __restrict__ w) {
    int idx = blockIdx.x * 256 + threadIdx.x;
    if (idx < OC_ * KTOT / 8) {
        int o = idx / (KTOT / 8), seg = idx - o * (KTOT / 8);
        int k0 = seg * 8;
        __half h[8];
#pragma unroll
        for (int i = 0; i < 8; i++) {
            int k = k0 + i;
            h[i] = __float2half((k < KREAL) ? w[o * KREAL + k] : 0.0f);
        }
        *(uint4*)&g_Wh[o * KTOT + k0] = *(uint4*)h;
    }
    if (idx < B_ * HW_) {
        float ssv = 0.0f;
#pragma unroll
        for (int g = 0; g < NG; g++) ssv += g_sspart[g * B_ * HW_ + idx];
        g_inv[idx] = 1.0f / fmaxf(sqrtf(ssv), 1e-12f);
    }
}

// ============================================================
// corr partials + sumsq + fp16 feature write (validated R14 version).
// ============================================================
#define CORR_BUF (4 * 36 * 40)
#define CORR_SMEM (3 * CORR_BUF * 4)

__global__ __launch_bounds__(256, 2) void corr_kernel(const float* __restrict__ feat) {
    extern __shared__ float tile[];

    const int tid = threadIdx.x;
    const int tx = tid & 15, ty = tid >> 4;
    const int x0 = blockIdx.x * 32, y0 = blockIdx.y * 32;
    const int b = blockIdx.z >> 3, g = blockIdx.z & 7;
    const float* fb = feat + (size_t)b * C_ * HW_;
    __half* ah = g_Ah + ((size_t)b * KTOT << 12);
    const int cbase = g * 128;

    u64t acc2[25][2];
    u64t ss2[2];
#pragma unroll
    for (int j = 0; j < 25; j++) { acc2[j][0] = 0ull; acc2[j][1] = 0ull; }
    ss2[0] = 0ull; ss2[1] = 0ull;

    auto load4 = [&](int c0, int buf) {
        float* base = tile + buf * CORR_BUF;
#pragma unroll 2
        for (int u = tid; u < 1440; u += 256) {
            int cc = u / 360, pos = u - cc * 360;
            int j = pos / 10, i = pos - j * 10;
            int gy = y0 - 2 + j;
            int gx0 = x0 - 4 + i * 4;
            bool valid = ((unsigned)gy < 64u) && ((unsigned)gx0 < 64u);
            const float* src = fb + (size_t)(c0 + cc) * HW_ + (valid ? (gy * 64 + gx0) : 0);
            unsigned dst = (unsigned)__cvta_generic_to_shared(base + cc * 1440 + j * 40 + i * 4);
            int sz = valid ? 16 : 0;
            asm volatile("cp.async.ca.shared.global [%0], [%1], 16, %2;\n"
                         :: "r"(dst), "l"(src), "r"(sz));
        }
    };

    load4(cbase, 0);
    asm volatile("cp.async.commit_group;\n");
    load4(cbase + 4, 1);
    asm volatile("cp.async.commit_group;\n");

    for (int it = 0; it < 32; ++it) {
        asm volatile("cp.async.wait_group 1;\n");
        __syncthreads();
        if (it + 2 < 32) load4(cbase + (it + 2) * 4, (it + 2) % 3);
        asm volatile("cp.async.commit_group;\n");

        const float* tb = tile + (it % 3) * CORR_BUF;
#pragma unroll
        for (int q = 0; q < 4; q++) {
            const float* tq = tb + q * 1440;
            const int c = cbase + it * 4 + q;

            float2 P2[3], P3[3];
            {
                const float* r2 = &tq[(2 * ty + 2) * 40 + 2 * tx + 2];
#pragma unroll
                for (int i = 0; i < 3; i++) {
                    P2[i] = *(const float2*)(r2 + 2 * i);
                    P3[i] = *(const float2*)(r2 + 40 + 2 * i);
                }
            }
            u64t cen2[2];
            cen2[0] = pk2(P2[1].x, P2[1].y);
            cen2[1] = pk2(P3[1].x, P3[1].y);
            fma2(ss2[0], cen2[0], cen2[0]);
            fma2(ss2[1], cen2[1], cen2[1]);
            {
                __half2 h0 = __floats2half2_rn(P2[1].x, P2[1].y);
                __half2 h1 = __floats2half2_rn(P3[1].x, P3[1].y);
                *(__half2*)&ah[((size_t)c << 12) + (y0 + 2 * ty + 0) * 64 + x0 + 2 * tx] = h0;
                *(__half2*)&ah[((size_t)c << 12) + (y0 + 2 * ty + 1) * 64 + x0 + 2 * tx] = h1;
            }
#pragma unroll
            for (int rr = 0; rr < 6; rr++) {
                float2 p0, p1, p2;
                if (rr == 2)      { p0 = P2[0]; p1 = P2[1]; p2 = P2[2]; }
                else if (rr == 3) { p0 = P3[0]; p1 = P3[1]; p2 = P3[2]; }
                else {
                    const float* rp = &tq[(2 * ty + rr) * 40 + 2 * tx + 2];
                    p0 = *(const float2*)(rp);
                    p1 = *(const float2*)(rp + 2);
                    p2 = *(const float2*)(rp + 4);
                }
                u64t t[5];
                t[0] = pk2(p0.x, p0.y);
                t[1] = pk2(p0.y, p1.x);
                t[2] = pk2(p1.x, p1.y);
                t[3] = pk2(p1.y, p2.x);
                t[4] = pk2(p2.x, p2.y);
#pragma unroll
                for (int cc = 0; cc < 5; cc++) {
                    if (rr <= 4) fma2(acc2[cc * 5 + rr][0], t[cc], cen2[0]);
                    if (rr >= 1) fma2(acc2[cc * 5 + rr - 1][1], t[cc], cen2[1]);
                }
            }
        }
    }

#pragma unroll
    for (int yy = 0; yy < 2; yy++) {
        int p = (y0 + 2 * ty + yy) * 64 + x0 + 2 * tx;
        *(float2*)&g_sspart[(g * B_ + b) * HW_ + p] = up2(ss2[yy]);
#pragma unroll
        for (int j = 0; j < 25; j++)
            *(float2*)&g_accpart[((size_t)(g * B_ + b) * 25 + j) * HW_ + p] = up2(acc2[j][yy]);
    }
}

// ============================================================
// combine: normalized corr -> fp16 A channels 1024..1055 (2 px/thread)
// ============================================================
__global__ void combine_kernel() {
    int idx = blockIdx.x * 256 + threadIdx.x;
    if (idx >= B_ * 32 * HW_ / 2) return;
    int ph = idx & (HW_ / 2 - 1);
    int j = (idx >> 11) & 31;
    int b = idx >> 16;
    int p = ph * 2;
    float2 v = make_float2(0.0f, 0.0f);
    if (j < 25) {
        int y = p >> 6, x = p & 63;
        int ccs = j / 5, r = j - ccs * 5;
        int tyy = y + r - 2;
        if ((unsigned)tyy < 64u) {
            float2 a = make_float2(0.0f, 0.0f);
#pragma unroll
            for (int g = 0; g < NG; g++) {
                float2 t = *(const float2*)&g_accpart[((size_t)(g * B_ + b) * 25 + j) * HW_ + p];
                a.x += t.x; a.y += t.y;
            }
            float2 ic = *(const float2*)&g_inv[b * HW_ + p];
            int txx0 = x + ccs - 2, txx1 = txx0 + 1;
            if ((unsigned)txx0 < 64u)
                v.x = a.x * ic.x * g_inv[b * HW_ + tyy * 64 + txx0];
            if ((unsigned)txx1 < 64u)
                v.y = a.y * ic.y * g_inv[b * HW_ + tyy * 64 + txx1];
        }
    }
    *(__half2*)&g_Ah[((size_t)(b * KTOT + C_ + j) << 12) + p] = __floats2half2_rn(v.x, v.y);
}

// ============================================================
// GEMM  out[b,o,p] = relu( sum_k Wh[o,k]*Ah[b,k,p] + bias[o] )
// CTA tile 128p x 128o x 64k, 128 threads (4 warps, 2x2), warp tile 64x64,
// 3-stage cp.async, 2 CTAs/SM. Last k-tile half depth.
// ============================================================
#define NKT 17
#define A_STAGE 17408       // 64*136*2
#define B_STAGE 18432       // 128*72*2
#define NSTG 3
#define GEMM_SMEM (NSTG * (A_STAGE + B_STAGE))

__global__ __launch_bounds__(128, 2) void gemm_kernel(const float* __restrict__ bias,
                                                      float* __restrict__ out) {
    extern __shared__ __align__(16) unsigned char SM[];
    __half* As[NSTG];
    __half* Bs[NSTG];
#pragma unroll
    for (int s = 0; s < NSTG; s++) {
        As[s] = (__half*)(SM + s * (A_STAGE + B_STAGE));
        Bs[s] = (__half*)(SM + s * (A_STAGE + B_STAGE) + A_STAGE);
    }
    float* Ep = (float*)SM;   // [128][33] epilogue staging

    const int tid = threadIdx.x;
    const int lane = tid & 31, wid = tid >> 5;
    const int wm = wid & 1, wn = wid >> 1;         // 2 warps along m, 2 along n
    const int o0 = blockIdx.x * 128;
    const int p0 = blockIdx.y * 128;
    const int b  = blockIdx.z;

    const __half* aBase = g_Ah + ((size_t)b * KTOT << 12) + p0;

    float accv[4][8][4];                           // fm x (fp*2+hh) x e = 128 floats
#pragma unroll
    for (int i = 0; i < 4; i++)
#pragma unroll
        for (int j = 0; j < 8; j++)
#pragma unroll
            for (int e = 0; e < 4; e++) accv[i][j][e] = 0.0f;

    auto loadStage = [&](int kt, int buf) {
        const bool last = (kt == NKT - 1);
        // A: [k 64][m 128] fp16 -> 1024 chunks (last: 32 rows -> 512)
#pragma unroll
        for (int s = 0; s < 8; s++) {
            if (last && s >= 4) break;
            int u = tid + s * 128;
            int row = u >> 4, ch = u & 15;
            const __half* src = aBase + (((size_t)(kt * 64 + row)) << 12) + ch * 8;
            unsigned dst = (unsigned)__cvta_generic_to_shared(As[buf] + row * 136 + ch * 8);
            asm volatile("cp.async.cg.shared.global [%0], [%1], 16;\n" :: "r"(dst), "l"(src));
        }
        // B: [n 128][k 64] fp16 -> 1024 chunks (last: k cols 0..31)
#pragma unroll
        for (int s = 0; s < 8; s++) {
            int u = tid + s * 128;
            int orow = u >> 3, q = u & 7;
            if (last && q >= 4) continue;
            const __half* src = g_Wh + (size_t)(o0 + orow) * KTOT + kt * 64 + q * 8;
            unsigned dst = (unsigned)__cvta_generic_to_shared(Bs[buf] + orow * 72 + q * 8);
            asm volatile("cp.async.cg.shared.global [%0], [%1], 16;\n" :: "r"(dst), "l"(src));
        }
        asm volatile("cp.async.commit_group;\n");
    };

    auto compute = [&](int buf, auto nksC) {
        constexpr int NKS = decltype(nksC)::value;
#pragma unroll
        for (int ks = 0; ks < NKS; ks++) {
            const int kb = ks * 16;
            unsigned a[4][4];
#pragma unroll
            for (int fm = 0; fm < 4; fm++) {
                int kk = kb + ((lane >> 4) & 1) * 8 + (lane & 7);
                int mm = wm * 64 + fm * 16 + ((lane >> 3) & 1) * 8;
                unsigned addr = (unsigned)__cvta_generic_to_shared(As[buf] + kk * 136 + mm);
                asm volatile("ldmatrix.sync.aligned.m8n8.x4.trans.shared.b16 {%0,%1,%2,%3}, [%4];\n"
                             : "=r"(a[fm][0]), "=r"(a[fm][1]), "=r"(a[fm][2]), "=r"(a[fm][3])
                             : "r"(addr));
            }
            unsigned bf[4][4];
#pragma unroll
            for (int fp = 0; fp < 4; fp++) {
                int row = wn * 64 + fp * 16 + (lane & 7) + ((lane >> 4) & 1) * 8;
                int kcol = kb + ((lane >> 3) & 1) * 8;
                unsigned addr = (unsigned)__cvta_generic_to_shared(Bs[buf] + row * 72 + kcol);
                asm volatile("ldmatrix.sync.aligned.m8n8.x4.shared.b16 {%0,%1,%2,%3}, [%4];\n"
                             : "=r"(bf[fp][0]), "=r"(bf[fp][1]), "=r"(bf[fp][2]), "=r"(bf[fp][3])
                             : "r"(addr));
            }
#pragma unroll
            for (int fm = 0; fm < 4; fm++)
#pragma unroll
                for (int fp = 0; fp < 4; fp++)
#pragma unroll
                    for (int hh = 0; hh < 2; hh++) {
                        float* c = accv[fm][fp * 2 + hh];
                        asm volatile(
                            "mma.sync.aligned.m16n8k16.row.col.f32.f16.f16.f32 "
                            "{%0,%1,%2,%3}, {%4,%5,%6,%7}, {%8,%9}, {%0,%1,%2,%3};\n"
                            : "+f"(c[0]), "+f"(c[1]), "+f"(c[2]), "+f"(c[3])
                            : "r"(a[fm][0]), "r"(a[fm][1]), "r"(a[fm][2]), "r"(a[fm][3]),
                              "r"(bf[fp][hh * 2]), "r"(bf[fp][hh * 2 + 1]));
                    }
        }
    };

    loadStage(0, 0);
    loadStage(1, 1);

    for (int kt = 0; kt < NKT; ++kt) {
        asm volatile("cp.async.wait_group 1;\n");
        __syncthreads();
        if (kt + 2 < NKT) loadStage(kt + 2, (kt + 2) % NSTG);
        else asm volatile("cp.async.commit_group;\n");
        if (kt < NKT - 1) compute(kt % NSTG, IC<4>{});
        else              compute(kt % NSTG, IC<2>{});
    }

    // epilogue: o-chunks of 32 staged via shared for coalesced [o][p] stores
    __syncthreads();
#pragma unroll
    for (int ci = 0; ci < 4; ci++) {
        if (wn == (ci >> 1)) {
            const int fbase = (ci & 1) * 4;
#pragma unroll
            for (int fm = 0; fm < 4; fm++)
#pragma unroll
                for (int f = 0; f < 4; f++) {
                    int fn = fbase + f;
#pragma unroll
                    for (int e = 0; e < 4; e++) {
                        int row = wm * 64 + fm * 16 + (lane >> 2) + (e >> 1) * 8;
                        int col = f * 8 + 2 * (lane & 3) + (e & 1);
                        Ep[row * 33 + col] = accv[fm][fn][e];
                    }
                }
        }
        __syncthreads();
        for (int idx = tid; idx < 32 * 128; idx += 128) {
            int ol = idx >> 7, m = idx & 127;
            int o = o0 + ci * 32 + ol;
            float v = Ep[m * 33 + ol] + bias[o];
            out[(((size_t)(b * OC_ + o)) << 12) + p0 + m] = fmaxf(v, 0.0f);
        }
        __syncthreads();
    }
}

// ============================================================
extern "C" void kernel_launch(void* const* d_in, const int* in_sizes, int n_in,
                              void* d_out, int out_size) {
    const float* feat = (const float*)d_in[0];
    const float* w    = (const float*)d_in[1];
    const float* bias = (const float*)d_in[2];
    float* out = (float*)d_out;

    static bool attr_set = false;
    if (!attr_set) {
        cudaFuncSetAttribute(gemm_kernel, cudaFuncAttributeMaxDynamicSharedMemorySize,
                             GEMM_SMEM);
        cudaFuncSetAttribute(corr_kernel, cudaFuncAttributeMaxDynamicSharedMemorySize,
                             CORR_SMEM);
        attr_set = true;
    }

    corr_kernel<<<dim3(2, 2, B_ * NG), 256, CORR_SMEM>>>(feat);       // launch 1
    fuse_kernel<<<(OC_ * KTOT / 8 + 255) / 256, 256>>>(w);            // launch 2
    combine_kernel<<<(B_ * 32 * HW_ / 2) / 256, 256>>>();             // launch 3
    gemm_kernel<<<dim3(8, 32, B_), 128, GEMM_SMEM>>>(bias, out);      // launch 4 (captured)
}

// round 16
// speedup vs baseline: 1.1364x; 1.0207x over previous
#include <cuda_runtime.h>
#include <cuda_fp16.h>
#include <cstdint>
#include <math.h>

// feature: [8,1024,64,64] f32 ; conv_w: [1024,1049] ; conv_b: [1024] ; out f32 same shape
// cat channels: 0..1023 feature, 1024..1048 corr (j = cc*5+r). K padded to 1088 for layout;
// only k<1056 is ever computed (W zero for k>=1049).

#define B_      8
#define C_      1024
#define HW_     4096
#define OC_     1024
#define KTOT    1088      // layout stride (17 * 64)
#define KREAL   1049
#define NG      8

template<int N> struct IC { static constexpr int value = N; };

// ---------------- scratch ----------------
__device__ __half g_Wh[OC_ * KTOT];                          // fp16 weights, zero-padded
__device__ __half g_Ah[(size_t)B_ * KTOT * HW_];             // fp16 A [b][1088][4096]
__device__ __align__(16) float g_sspart[NG * B_ * HW_];
__device__ __align__(16) float g_inv[B_ * HW_];
__device__ __align__(16) float g_accpart[(size_t)NG * B_ * 25 * HW_];

// ---------------- f32x2 helpers ----------------
typedef unsigned long long u64t;
__device__ __forceinline__ u64t pk2(float a, float b) {
    u64t r; asm("mov.b64 %0, {%1, %2};" : "=l"(r) : "f"(a), "f"(b)); return r;
}
__device__ __forceinline__ void fma2(u64t& d, u64t a, u64t b) {
    asm("fma.rn.f32x2 %0, %1, %2, %0;" : "+l"(d) : "l"(a), "l"(b));
}
__device__ __forceinline__ float2 up2(u64t a) {
    float2 r; asm("mov.b64 {%0, %1}, %2;" : "=f"(r.x), "=f"(r.y) : "l"(a)); return r;
}

// ============================================================
// fused: convW (vectorized, conv_w -> fp16 padded) + inv
// ============================================================
__global__ void fuse_kernel(const float* __restrict__ w) {
    int idx = blockIdx.x * 256 + threadIdx.x;
    if (idx < OC_ * KTOT / 8) {
        int o = idx / (KTOT / 8), seg = idx - o * (KTOT / 8);
        int k0 = seg * 8;
        __half h[8];
#pragma unroll
        for (int i = 0; i < 8; i++) {
            int k = k0 + i;
            h[i] = __float2half((k < KREAL) ? w[o * KREAL + k] : 0.0f);
        }
        *(uint4*)&g_Wh[o * KTOT + k0] = *(uint4*)h;
    }
    if (idx < B_ * HW_) {
        float ssv = 0.0f;
#pragma unroll
        for (int g = 0; g < NG; g++) ssv += g_sspart[g * B_ * HW_ + idx];
        g_inv[idx] = 1.0f / fmaxf(sqrtf(ssv), 1e-12f);
    }
}

// ============================================================
// corr partials + sumsq + fp16 feature write.
// 32x32 tile, 2x2 px/thread, f32x2 FMA, NG=8 groups of 128 ch.
// 4 smem buffers, lookahead 3, one __syncthreads/iter.
// ============================================================
#define CORR_BUF (4 * 36 * 40)
#define CORR_NB 4
#define CORR_SMEM (CORR_NB * CORR_BUF * 4)     // 92160 B

__global__ __launch_bounds__(256, 2) void corr_kernel(const float* __restrict__ feat) {
    extern __shared__ float tile[];

    const int tid = threadIdx.x;
    const int tx = tid & 15, ty = tid >> 4;
    const int x0 = blockIdx.x * 32, y0 = blockIdx.y * 32;
    const int b = blockIdx.z >> 3, g = blockIdx.z & 7;
    const float* fb = feat + (size_t)b * C_ * HW_;
    __half* ah = g_Ah + ((size_t)b * KTOT << 12);
    const int cbase = g * 128;

    u64t acc2[25][2];
    u64t ss2[2];
#pragma unroll
    for (int j = 0; j < 25; j++) { acc2[j][0] = 0ull; acc2[j][1] = 0ull; }
    ss2[0] = 0ull; ss2[1] = 0ull;

    auto load4 = [&](int c0, int buf) {
        float* base = tile + buf * CORR_BUF;
#pragma unroll 2
        for (int u = tid; u < 1440; u += 256) {
            int cc = u / 360, pos = u - cc * 360;
            int j = pos / 10, i = pos - j * 10;
            int gy = y0 - 2 + j;
            int gx0 = x0 - 4 + i * 4;
            bool valid = ((unsigned)gy < 64u) && ((unsigned)gx0 < 64u);
            const float* src = fb + (size_t)(c0 + cc) * HW_ + (valid ? (gy * 64 + gx0) : 0);
            unsigned dst = (unsigned)__cvta_generic_to_shared(base + cc * 1440 + j * 40 + i * 4);
            int sz = valid ? 16 : 0;
            asm volatile("cp.async.ca.shared.global [%0], [%1], 16, %2;\n"
                         :: "r"(dst), "l"(src), "r"(sz));
        }
    };

    load4(cbase, 0);
    asm volatile("cp.async.commit_group;\n");
    load4(cbase + 4, 1);
    asm volatile("cp.async.commit_group;\n");
    load4(cbase + 8, 2);
    asm volatile("cp.async.commit_group;\n");

    for (int it = 0; it < 32; ++it) {
        // pending groups are it+1, it+2 (plus instantly-complete empties)
        asm volatile("cp.async.wait_group 2;\n");
        __syncthreads();
        if (it + 3 < 32) load4(cbase + (it + 3) * 4, (it + 3) % CORR_NB);
        asm volatile("cp.async.commit_group;\n");    // real or empty

        const float* tb = tile + (it % CORR_NB) * CORR_BUF;
#pragma unroll
        for (int q = 0; q < 4; q++) {
            const float* tq = tb + q * 1440;
            const int c = cbase + it * 4 + q;

            float2 P2[3], P3[3];
            {
                const float* r2 = &tq[(2 * ty + 2) * 40 + 2 * tx + 2];
#pragma unroll
                for (int i = 0; i < 3; i++) {
                    P2[i] = *(const float2*)(r2 + 2 * i);
                    P3[i] = *(const float2*)(r2 + 40 + 2 * i);
                }
            }
            u64t cen2[2];
            cen2[0] = pk2(P2[1].x, P2[1].y);
            cen2[1] = pk2(P3[1].x, P3[1].y);
            fma2(ss2[0], cen2[0], cen2[0]);
            fma2(ss2[1], cen2[1], cen2[1]);
            {
                __half2 h0 = __floats2half2_rn(P2[1].x, P2[1].y);
                __half2 h1 = __floats2half2_rn(P3[1].x, P3[1].y);
                *(__half2*)&ah[((size_t)c << 12) + (y0 + 2 * ty + 0) * 64 + x0 + 2 * tx] = h0;
                *(__half2*)&ah[((size_t)c << 12) + (y0 + 2 * ty + 1) * 64 + x0 + 2 * tx] = h1;
            }
#pragma unroll
            for (int rr = 0; rr < 6; rr++) {
                float2 p0, p1, p2;
                if (rr == 2)      { p0 = P2[0]; p1 = P2[1]; p2 = P2[2]; }
                else if (rr == 3) { p0 = P3[0]; p1 = P3[1]; p2 = P3[2]; }
                else {
                    const float* rp = &tq[(2 * ty + rr) * 40 + 2 * tx + 2];
                    p0 = *(const float2*)(rp);
                    p1 = *(const float2*)(rp + 2);
                    p2 = *(const float2*)(rp + 4);
                }
                u64t t[5];
                t[0] = pk2(p0.x, p0.y);
                t[1] = pk2(p0.y, p1.x);
                t[2] = pk2(p1.x, p1.y);
                t[3] = pk2(p1.y, p2.x);
                t[4] = pk2(p2.x, p2.y);
#pragma unroll
                for (int cc = 0; cc < 5; cc++) {
                    if (rr <= 4) fma2(acc2[cc * 5 + rr][0], t[cc], cen2[0]);
                    if (rr >= 1) fma2(acc2[cc * 5 + rr - 1][1], t[cc], cen2[1]);
                }
            }
        }
    }

#pragma unroll
    for (int yy = 0; yy < 2; yy++) {
        int p = (y0 + 2 * ty + yy) * 64 + x0 + 2 * tx;
        *(float2*)&g_sspart[(g * B_ + b) * HW_ + p] = up2(ss2[yy]);
#pragma unroll
        for (int j = 0; j < 25; j++)
            *(float2*)&g_accpart[((size_t)(g * B_ + b) * 25 + j) * HW_ + p] = up2(acc2[j][yy]);
    }
}

// ============================================================
// combine: normalized corr -> fp16 A channels 1024..1055 (2 px/thread)
// ============================================================
__global__ void combine_kernel() {
    int idx = blockIdx.x * 256 + threadIdx.x;
    if (idx >= B_ * 32 * HW_ / 2) return;
    int ph = idx & (HW_ / 2 - 1);
    int j = (idx >> 11) & 31;
    int b = idx >> 16;
    int p = ph * 2;
    float2 v = make_float2(0.0f, 0.0f);
    if (j < 25) {
        int y = p >> 6, x = p & 63;
        int ccs = j / 5, r = j - ccs * 5;
        int tyy = y + r - 2;
        if ((unsigned)tyy < 64u) {
            float2 a = make_float2(0.0f, 0.0f);
#pragma unroll
            for (int g = 0; g < NG; g++) {
                float2 t = *(const float2*)&g_accpart[((size_t)(g * B_ + b) * 25 + j) * HW_ + p];
                a.x += t.x; a.y += t.y;
            }
            float2 ic = *(const float2*)&g_inv[b * HW_ + p];
            int txx0 = x + ccs - 2, txx1 = txx0 + 1;
            if ((unsigned)txx0 < 64u)
                v.x = a.x * ic.x * g_inv[b * HW_ + tyy * 64 + txx0];
            if ((unsigned)txx1 < 64u)
                v.y = a.y * ic.y * g_inv[b * HW_ + tyy * 64 + txx1];
        }
    }
    *(__half2*)&g_Ah[((size_t)(b * KTOT + C_ + j) << 12) + p] = __floats2half2_rn(v.x, v.y);
}

// ============================================================
// GEMM  out[b,o,p] = relu( sum_k Wh[o,k]*Ah[b,k,p] + bias[o] )
// CTA tile 128p x 128o x 64k, 128 threads (4 warps, 2x2), warp tile 64x64,
// 3-stage cp.async, 2 CTAs/SM, fragment double-buffer across k16 steps.
// Last k-tile half depth.
// ============================================================
#define NKT 17
#define A_STAGE 17408       // 64*136*2
#define B_STAGE 18432       // 128*72*2
#define NSTG 3
#define GEMM_SMEM (NSTG * (A_STAGE + B_STAGE))

__global__ __launch_bounds__(128, 2) void gemm_kernel(const float* __restrict__ bias,
                                                      float* __restrict__ out) {
    extern __shared__ __align__(16) unsigned char SM[];
    __half* As[NSTG];
    __half* Bs[NSTG];
#pragma unroll
    for (int s = 0; s < NSTG; s++) {
        As[s] = (__half*)(SM + s * (A_STAGE + B_STAGE));
        Bs[s] = (__half*)(SM + s * (A_STAGE + B_STAGE) + A_STAGE);
    }
    float* Ep = (float*)SM;   // [128][33] epilogue staging

    const int tid = threadIdx.x;
    const int lane = tid & 31, wid = tid >> 5;
    const int wm = wid & 1, wn = wid >> 1;         // 2 warps along m, 2 along n
    const int o0 = blockIdx.x * 128;
    const int p0 = blockIdx.y * 128;
    const int b  = blockIdx.z;

    const __half* aBase = g_Ah + ((size_t)b * KTOT << 12) + p0;

    float accv[4][8][4];                           // 128 floats
#pragma unroll
    for (int i = 0; i < 4; i++)
#pragma unroll
        for (int j = 0; j < 8; j++)
#pragma unroll
            for (int e = 0; e < 4; e++) accv[i][j][e] = 0.0f;

    auto loadStage = [&](int kt, int buf) {
        const bool last = (kt == NKT - 1);
#pragma unroll
        for (int s = 0; s < 8; s++) {
            if (last && s >= 4) break;
            int u = tid + s * 128;
            int row = u >> 4, ch = u & 15;
            const __half* src = aBase + (((size_t)(kt * 64 + row)) << 12) + ch * 8;
            unsigned dst = (unsigned)__cvta_generic_to_shared(As[buf] + row * 136 + ch * 8);
            asm volatile("cp.async.cg.shared.global [%0], [%1], 16;\n" :: "r"(dst), "l"(src));
        }
#pragma unroll
        for (int s = 0; s < 8; s++) {
            int u = tid + s * 128;
            int orow = u >> 3, q = u & 7;
            if (last && q >= 4) continue;
            const __half* src = g_Wh + (size_t)(o0 + orow) * KTOT + kt * 64 + q * 8;
            unsigned dst = (unsigned)__cvta_generic_to_shared(Bs[buf] + orow * 72 + q * 8);
            asm volatile("cp.async.cg.shared.global [%0], [%1], 16;\n" :: "r"(dst), "l"(src));
        }
        asm volatile("cp.async.commit_group;\n");
    };

    // load all 8 ldmatrix fragments for one k16 step
    auto ldFrag = [&](int buf, int ks, unsigned (&a)[4][4], unsigned (&bf)[4][4]) {
        const int kb = ks * 16;
#pragma unroll
        for (int fm = 0; fm < 4; fm++) {
            int kk = kb + ((lane >> 4) & 1) * 8 + (lane & 7);
            int mm = wm * 64 + fm * 16 + ((lane >> 3) & 1) * 8;
            unsigned addr = (unsigned)__cvta_generic_to_shared(As[buf] + kk * 136 + mm);
            asm volatile("ldmatrix.sync.aligned.m8n8.x4.trans.shared.b16 {%0,%1,%2,%3}, [%4];\n"
                         : "=r"(a[fm][0]), "=r"(a[fm][1]), "=r"(a[fm][2]), "=r"(a[fm][3])
                         : "r"(addr));
        }
#pragma unroll
        for (int fp = 0; fp < 4; fp++) {
            int row = wn * 64 + fp * 16 + (lane & 7) + ((lane >> 4) & 1) * 8;
            int kcol = kb + ((lane >> 3) & 1) * 8;
            unsigned addr = (unsigned)__cvta_generic_to_shared(Bs[buf] + row * 72 + kcol);
            asm volatile("ldmatrix.sync.aligned.m8n8.x4.shared.b16 {%0,%1,%2,%3}, [%4];\n"
                         : "=r"(bf[fp][0]), "=r"(bf[fp][1]), "=r"(bf[fp][2]), "=r"(bf[fp][3])
                         : "r"(addr));
        }
    };

    auto doMMA = [&](unsigned (&a)[4][4], unsigned (&bf)[4][4]) {
#pragma unroll
        for (int fm = 0; fm < 4; fm++)
#pragma unroll
            for (int fp = 0; fp < 4; fp++)
#pragma unroll
                for (int hh = 0; hh < 2; hh++) {
                    float* c = accv[fm][fp * 2 + hh];
                    asm volatile(
                        "mma.sync.aligned.m16n8k16.row.col.f32.f16.f16.f32 "
                        "{%0,%1,%2,%3}, {%4,%5,%6,%7}, {%8,%9}, {%0,%1,%2,%3};\n"
                        : "+f"(c[0]), "+f"(c[1]), "+f"(c[2]), "+f"(c[3])
                        : "r"(a[fm][0]), "r"(a[fm][1]), "r"(a[fm][2]), "r"(a[fm][3]),
                          "r"(bf[fp][hh * 2]), "r"(bf[fp][hh * 2 + 1]));
                }
    };

    auto compute = [&](int buf, auto nksC) {
        constexpr int NKS = decltype(nksC)::value;
        unsigned aF[2][4][4], bF[2][4][4];
        ldFrag(buf, 0, aF[0], bF[0]);
#pragma unroll
        for (int ks = 0; ks < NKS; ks++) {
            if (ks + 1 < NKS) ldFrag(buf, ks + 1, aF[(ks + 1) & 1], bF[(ks + 1) & 1]);
            doMMA(aF[ks & 1], bF[ks & 1]);
        }
    };

    loadStage(0, 0);
    loadStage(1, 1);

    for (int kt = 0; kt < NKT; ++kt) {
        asm volatile("cp.async.wait_group 1;\n");
        __syncthreads();
        if (kt + 2 < NKT) loadStage(kt + 2, (kt + 2) % NSTG);
        else asm volatile("cp.async.commit_group;\n");
        if (kt < NKT - 1) compute(kt % NSTG, IC<4>{});
        else              compute(kt % NSTG, IC<2>{});
    }

    // epilogue: o-chunks of 32 staged via shared for coalesced [o][p] stores
    __syncthreads();
#pragma unroll
    for (int ci = 0; ci < 4; ci++) {
        if (wn == (ci >> 1)) {
            const int fbase = (ci & 1) * 4;
#pragma unroll
            for (int fm = 0; fm < 4; fm++)
#pragma unroll
                for (int f = 0; f < 4; f++) {
                    int fn = fbase + f;
#pragma unroll
                    for (int e = 0; e < 4; e++) {
                        int row = wm * 64 + fm * 16 + (lane >> 2) + (e >> 1) * 8;
                        int col = f * 8 + 2 * (lane & 3) + (e & 1);
                        Ep[row * 33 + col] = accv[fm][fn][e];
                    }
                }
        }
        __syncthreads();
        for (int idx = tid; idx < 32 * 128; idx += 128) {
            int ol = idx >> 7, m = idx & 127;
            int o = o0 + ci * 32 + ol;
            float v = Ep[m * 33 + ol] + bias[o];
            out[(((size_t)(b * OC_ + o)) << 12) + p0 + m] = fmaxf(v, 0.0f);
        }
        __syncthreads();
    }
}

// ============================================================
extern "C" void kernel_launch(void* const* d_in, const int* in_sizes, int n_in,
                              void* d_out, int out_size) {
    const float* feat = (const float*)d_in[0];
    const float* w    = (const float*)d_in[1];
    const float* bias = (const float*)d_in[2];
    float* out = (float*)d_out;

    static bool attr_set = false;
    if (!attr_set) {
        cudaFuncSetAttribute(gemm_kernel, cudaFuncAttributeMaxDynamicSharedMemorySize,
                             GEMM_SMEM);
        cudaFuncSetAttribute(corr_kernel, cudaFuncAttributeMaxDynamicSharedMemorySize,
                             CORR_SMEM);
        attr_set = true;
    }

    corr_kernel<<<dim3(2, 2, B_ * NG), 256, CORR_SMEM>>>(feat);       // launch 1
    fuse_kernel<<<(OC_ * KTOT / 8 + 255) / 256, 256>>>(w);            // launch 2
    combine_kernel<<<(B_ * 32 * HW_ / 2) / 256, 256>>>();             // launch 3
    gemm_kernel<<<dim3(8, 32, B_), 128, GEMM_SMEM>>>(bias, out);      // launch 4 (captured)
}